// round 16
// baseline (speedup 1.0000x reference)
#include <cuda_runtime.h>
#include <cuda_fp16.h>
#include <math.h>
#include <stdint.h>

// Problem constants
#define B_  64
#define T_  1024
#define C_  256
#define BR  64               // query rows per CTA (= key tile)
#define NTILE (T_ / BR)      // 16
#define OSS 260              // final O staging stride (floats)

// SMEM byte offsets (per CTA ~100.5 KB -> 2 CTAs/SM)
#define OF_Q   0             // 64 rows x 528B
#define OF_X0  33792         // 64 rows x 528B (double-buffered gathered K=V)
#define OF_X1  67584
#define OF_MU  101376        // mu[64]
#define OF_RS  101632        // rstd[64]
#define OF_CS  101888        // colsum/1024 [256] (never aliased)
#define SMEM_TOTAL 102912

#define PAD_IDX 0x3FFFFFFF

// Device scratch
__device__ __half g_xh[B_ * T_ * C_];     // fp16 copy of x
__device__ __align__(512) __half g_zeroRow[C_];  // zero-init (static storage)
__device__ int    g_kidx[B_ * T_];        // orig index per compacted key slot (ASCENDING)
__device__ int    g_cnt[B_ * NTILE];      // # valid keys with idx < (qt+1)*64
__device__ int    g_done[B_];             // per-batch completion counter
__device__ float  g_cs64[B_ * 64 * C_];   // colsum partials (16-row groups)
__device__ float  g_colsum[B_ * C_];      // pre-scaled colsum/1024
__device__ float  g_part[B_ * NTILE * C_];

// ---------------------------------------------------------------------------
static __device__ __forceinline__ uint32_t smem_u32(const void* p) {
    return (uint32_t)__cvta_generic_to_shared(p);
}
static __device__ __forceinline__ void cp16(uint32_t dst, const void* src) {
    asm volatile("cp.async.cg.shared.global [%0], [%1], 16;" :: "r"(dst), "l"(src));
}
static __device__ __forceinline__ void ldsm4(
    uint32_t& r0, uint32_t& r1, uint32_t& r2, uint32_t& r3, uint32_t a)
{
    asm volatile("ldmatrix.sync.aligned.m8n8.x4.shared.b16 {%0,%1,%2,%3}, [%4];"
                 : "=r"(r0), "=r"(r1), "=r"(r2), "=r"(r3) : "r"(a));
}
static __device__ __forceinline__ void ldsm4t(
    uint32_t& r0, uint32_t& r1, uint32_t& r2, uint32_t& r3, uint32_t a)
{
    asm volatile("ldmatrix.sync.aligned.m8n8.x4.trans.shared.b16 {%0,%1,%2,%3}, [%4];"
                 : "=r"(r0), "=r"(r1), "=r"(r2), "=r"(r3) : "r"(a));
}
static __device__ __forceinline__ void mma_f16(
    float* d, uint32_t a0, uint32_t a1, uint32_t a2, uint32_t a3,
    uint32_t b0, uint32_t b1)
{
    asm volatile(
        "mma.sync.aligned.m16n8k16.row.col.f32.f16.f16.f32 "
        "{%0,%1,%2,%3},{%4,%5,%6,%7},{%8,%9},{%0,%1,%2,%3};"
        : "+f"(d[0]), "+f"(d[1]), "+f"(d[2]), "+f"(d[3])
        : "r"(a0), "r"(a1), "r"(a2), "r"(a3), "r"(b0), "r"(b1));
}
static __device__ __forceinline__ uint32_t packh2(float x, float y) {
    __half2 h = __floats2half2_rn(x, y);
    return *(uint32_t*)&h;
}

// ---------------------------------------------------------------------------
// Kernel 1: fp16 copy of x (vectorized) + fp32 colsum partials
// ---------------------------------------------------------------------------
__global__ void prep_kernel(const float* __restrict__ x) {
    const int b = blockIdx.x, ch = blockIdx.y, tid = threadIdx.x;
    const int c4 = (tid & 63) * 4;
    const int rg = tid >> 6;                  // 0..3
    const size_t row0 = (size_t)b * T_ + ch * 64 + rg * 16;
    float s0 = 0.f, s1 = 0.f, s2 = 0.f, s3 = 0.f;
#pragma unroll
    for (int i = 0; i < 16; i++) {
        const float4 v = *(const float4*)(x + (row0 + i) * C_ + c4);
        s0 += v.x; s1 += v.y; s2 += v.z; s3 += v.w;
        __half2 h0 = __floats2half2_rn(v.x, v.y);
        __half2 h1 = __floats2half2_rn(v.z, v.w);
        *(uint2*)(g_xh + (row0 + i) * C_ + c4) =
            make_uint2(*(uint32_t*)&h0, *(uint32_t*)&h1);
    }
    *(float4*)(g_cs64 + ((size_t)(b * 64 + ch * 4 + rg)) * C_ + c4) =
        make_float4(s0, s1, s2, s3);
}

// ---------------------------------------------------------------------------
// Kernel 1b: per-batch scan (prefix-sum of key mask) + colsum reduce + done=0
// ---------------------------------------------------------------------------
__global__ void scan_kernel(const int* __restrict__ km) {
    __shared__ int list[T_];
    __shared__ int wsum[8];
    __shared__ int incl[256];
    __shared__ int total_s;

    const int b = blockIdx.x, tid = threadIdx.x;
    const int lane = tid & 31, wp = tid >> 5;

    if (tid == 0) g_done[b] = 0;

    int4 f = ((const int4*)(km + b * T_))[tid];
    int c0 = (f.x != 0), c1 = (f.y != 0), c2 = (f.z != 0), c3 = (f.w != 0);
    int cnt4 = c0 + c1 + c2 + c3;

    int v = cnt4;
#pragma unroll
    for (int off = 1; off < 32; off <<= 1) {
        int n = __shfl_up_sync(0xffffffffu, v, off);
        if (lane >= off) v += n;
    }
    if (lane == 31) wsum[wp] = v;
    __syncthreads();
    if (tid == 0) {
        int running = 0;
#pragma unroll
        for (int i = 0; i < 8; i++) { int t = wsum[i]; wsum[i] = running; running += t; }
        total_s = running;
    }
    __syncthreads();
    const int excl = v - cnt4 + wsum[wp];
    incl[tid] = excl + cnt4;

    int base = excl;
    const int t0 = tid * 4;
    if (c0) list[base++] = t0;
    if (c1) list[base++] = t0 + 1;
    if (c2) list[base++] = t0 + 2;
    if (c3) list[base++] = t0 + 3;
    __syncthreads();

    if (tid < NTILE) g_cnt[b * NTILE + tid] = incl[(tid + 1) * 16 - 1];

    const int nv = total_s;
    const int nvp = (nv + 63) & ~63;
    for (int r = tid; r < nvp; r += 256)
        g_kidx[b * T_ + r] = (r < nv) ? list[r] : PAD_IDX;

    float s = 0.f;
#pragma unroll 8
    for (int i = 0; i < 64; i++) s += g_cs64[(size_t)(b * 64 + i) * C_ + tid];
    g_colsum[b * C_ + tid] = s * (1.f / 1024.f);
}

// ---------------------------------------------------------------------------
// Kernel 2: flash attention over compacted keys (gathered on load), fp16 mma,
// register P, in-register online softmax. Monotonic data-driven block skip:
// key indices ascend, so each warp needs only a PREFIX of the 4 blocks.
// Last CTA per batch does the final time-mean. 128 thr, 2 CTAs/SM.
// ---------------------------------------------------------------------------
__global__ void __launch_bounds__(128, 2)
attn_kernel(const float* __restrict__ gamma, const float* __restrict__ beta,
            float* __restrict__ out)
{
    extern __shared__ char smc[];
    __shared__ int lastflag;
    float* smf = (float*)smc;
    const uint32_t sb = smem_u32(smc);

    const int qt   = 15 - blockIdx.y;        // heavy tiles first
    const int b    = blockIdx.x;
    const int tid  = threadIdx.x;
    const int lane = tid & 31;
    const int w    = tid >> 5;
    const int jj   = lane & 3;
    const int g8   = lane >> 2;
    const int l15  = lane & 15;
    const int lh   = lane >> 4;
    const int q0   = qt * BR;
    const int row0 = w * 16 + g8;
    const int grow0 = q0 + row0, grow1 = grow0 + 8;
    const int gmax  = q0 + w * 16 + 15;       // warp's max causal row
    const __half* xb  = g_xh + (size_t)b * T_ * C_;
    const int*    kib = g_kidx + b * T_;

    const int cnt    = g_cnt[b * NTILE + qt];
    const int ntiles = (cnt + 63) >> 6;

    const uint32_t aQ = sb + OF_Q + (uint32_t)(w * 16 + l15) * 528 + lh * 16;

    // Prefetch Q (+ gathered key tile 0 if any)
#pragma unroll
    for (int it = 0; it < 16; it++) {
        int idx = tid + it * 128;
        int r = idx >> 5, g = idx & 31;
        cp16(sb + OF_Q + r * 528 + g * 16, xb + (size_t)(q0 + r) * C_ + g * 8);
    }
    if (ntiles > 0) {
#pragma unroll
        for (int it = 0; it < 16; it++) {
            int idx = tid + it * 128;
            int r = idx >> 5, g = idx & 31;
            const int orig = kib[r];
            const __half* src = (orig == PAD_IDX) ? g_zeroRow
                                                  : xb + (size_t)orig * C_;
            cp16(sb + OF_X0 + r * 528 + g * 16, src + g * 8);
        }
    }
    asm volatile("cp.async.commit_group;");

    float Oacc[32][4];
#pragma unroll
    for (int i = 0; i < 32; i++)
#pragma unroll
        for (int e = 0; e < 4; e++) Oacc[i][e] = 0.f;
    float m0 = -INFINITY, m1 = -INFINITY, l0 = 0.f, l1 = 0.f;

    for (int st = 0; st < ntiles; st++) {
        const uint32_t Xoff = (st & 1) ? OF_X1 : OF_X0;
        const int s0 = st * BR;

        // monotonic prefix cut: block nb live iff its first key <= gmax
        int nbcut = 0;
#pragma unroll
        for (int nb = 0; nb < 4; nb++)
            nbcut += (kib[s0 + 16 * nb] <= gmax) ? 1 : 0;

        asm volatile("cp.async.wait_group 0;");
        __syncthreads();                      // X[st] visible; other buffer free

        if (st + 1 < ntiles) {                // prefetch next gathered tile
            const uint32_t Xn = ((st + 1) & 1) ? OF_X1 : OF_X0;
            const int s0n = (st + 1) * BR;
#pragma unroll
            for (int it = 0; it < 16; it++) {
                int idx = tid + it * 128;
                int r = idx >> 5, g = idx & 31;
                const int orig = kib[s0n + r];
                const __half* src = (orig == PAD_IDX) ? g_zeroRow
                                                      : xb + (size_t)orig * C_;
                cp16(sb + Xn + r * 528 + g * 16, src + g * 8);
            }
            asm volatile("cp.async.commit_group;");
        }

        int2 kiv[8];
#pragma unroll
        for (int nt = 0; nt < 8; nt++)
            kiv[nt] = *(const int2*)(kib + s0 + nt * 8 + 2 * jj);

        // ---- Stage A: S = Q Kc^T, warp tile 16x64, prefix blocks only ----
        uint32_t aK[4];
#pragma unroll
        for (int nb = 0; nb < 4; nb++)
            aK[nb] = sb + Xoff + (uint32_t)(nb * 16 + (lane & 7) + lh * 8) * 528
                     + ((lane >> 3) & 1) * 16;

        float sacc[8][4];
#pragma unroll
        for (int nt = 0; nt < 8; nt++)
#pragma unroll
            for (int e = 0; e < 4; e++) sacc[nt][e] = 0.f;

#pragma unroll
        for (int k = 0; k < 16; k++) {
            uint32_t a0, a1, a2, a3;
            ldsm4(a0, a1, a2, a3, aQ + k * 32);
#pragma unroll
            for (int nb = 0; nb < 4; nb++) {
                if (nb < nbcut) {             // warp-uniform
                    uint32_t b0, b1, b2, b3;
                    ldsm4(b0, b1, b2, b3, aK[nb] + k * 32);
                    mma_f16(sacc[2 * nb],     a0, a1, a2, a3, b0, b1);
                    mma_f16(sacc[2 * nb + 1], a0, a1, a2, a3, b2, b3);
                }
            }
        }

        // ---- Mask + in-register online softmax ----
#pragma unroll
        for (int nt = 0; nt < 8; nt++) {
#pragma unroll
            for (int e = 0; e < 2; e++) {
                const int ki = e ? kiv[nt].y : kiv[nt].x;
                sacc[nt][e]     = (ki <= grow0) ? sacc[nt][e] * 0.0625f     : -INFINITY;
                sacc[nt][2 + e] = (ki <= grow1) ? sacc[nt][2 + e] * 0.0625f : -INFINITY;
            }
        }
        float mt0 = -INFINITY, mt1 = -INFINITY;
#pragma unroll
        for (int nt = 0; nt < 8; nt++) {
            mt0 = fmaxf(mt0, fmaxf(sacc[nt][0], sacc[nt][1]));
            mt1 = fmaxf(mt1, fmaxf(sacc[nt][2], sacc[nt][3]));
        }
        mt0 = fmaxf(mt0, __shfl_xor_sync(0xffffffffu, mt0, 1));
        mt0 = fmaxf(mt0, __shfl_xor_sync(0xffffffffu, mt0, 2));
        mt1 = fmaxf(mt1, __shfl_xor_sync(0xffffffffu, mt1, 1));
        mt1 = fmaxf(mt1, __shfl_xor_sync(0xffffffffu, mt1, 2));
        const float mn0 = fmaxf(m0, mt0), mn1 = fmaxf(m1, mt1);
        const float al0 = (m0 == -INFINITY) ? 0.f : __expf(m0 - mn0);
        const float al1 = (m1 == -INFINITY) ? 0.f : __expf(m1 - mn1);

        float p0[8][2], p1[8][2], sum0 = 0.f, sum1 = 0.f;
#pragma unroll
        for (int nt = 0; nt < 8; nt++) {
#pragma unroll
            for (int e = 0; e < 2; e++) {
                float a = sacc[nt][e],     pa = (a == -INFINITY) ? 0.f : __expf(a - mn0);
                float c = sacc[nt][2 + e], pc = (c == -INFINITY) ? 0.f : __expf(c - mn1);
                p0[nt][e] = pa; sum0 += pa;
                p1[nt][e] = pc; sum1 += pc;
            }
        }
        sum0 += __shfl_xor_sync(0xffffffffu, sum0, 1);
        sum0 += __shfl_xor_sync(0xffffffffu, sum0, 2);
        sum1 += __shfl_xor_sync(0xffffffffu, sum1, 1);
        sum1 += __shfl_xor_sync(0xffffffffu, sum1, 2);
        l0 = l0 * al0 + sum0;  m0 = mn0;
        l1 = l1 * al1 + sum1;  m1 = mn1;

#pragma unroll
        for (int i = 0; i < 32; i++) {
            Oacc[i][0] *= al0; Oacc[i][1] *= al0;
            Oacc[i][2] *= al1; Oacc[i][3] *= al1;
        }

        uint32_t pA[4][4];
#pragma unroll
        for (int kb = 0; kb < 4; kb++) {
            pA[kb][0] = packh2(p0[2 * kb][0],     p0[2 * kb][1]);
            pA[kb][1] = packh2(p1[2 * kb][0],     p1[2 * kb][1]);
            pA[kb][2] = packh2(p0[2 * kb + 1][0], p0[2 * kb + 1][1]);
            pA[kb][3] = packh2(p1[2 * kb + 1][0], p1[2 * kb + 1][1]);
        }

        // ---- Stage B: O += P @ Xc, prefix key-chunks only ----
        const uint32_t aXb = sb + Xoff + (uint32_t)l15 * 528 + lh * 16;
#pragma unroll
        for (int ks = 0; ks < 4; ks++) {
            if (ks < nbcut) {                 // warp-uniform; P==0 beyond cut
#pragma unroll
                for (int n16 = 0; n16 < 16; n16++) {
                    uint32_t x0, x1, x2, x3;
                    ldsm4t(x0, x1, x2, x3, aXb + ks * 16 * 528 + n16 * 32);
                    mma_f16(Oacc[2 * n16],     pA[ks][0], pA[ks][1], pA[ks][2], pA[ks][3], x0, x1);
                    mma_f16(Oacc[2 * n16 + 1], pA[ks][0], pA[ks][1], pA[ks][2], pA[ks][3], x2, x3);
                }
            }
        }
    }
    asm volatile("cp.async.wait_group 0;");    // drain (covers ntiles==0)

    // ---- colsum (pre-scaled, pre-reduced) -> never-aliased smem ----
    smf[OF_CS / 4 + tid]       = g_colsum[b * C_ + tid];
    smf[OF_CS / 4 + tid + 128] = g_colsum[b * C_ + tid + 128];

    // ---- Epilogue: normalize / degenerate fixup -> Os staging ----
    __syncthreads();
    float* Os = smf;
    const float* csum = smf + OF_CS / 4;
    {
        const bool d0 = (l0 == 0.f), d1 = (l1 == 0.f);
        const float inv0 = d0 ? 0.f : (1.f / l0);
        const float inv1 = d1 ? 0.f : (1.f / l1);
#pragma unroll
        for (int nt2 = 0; nt2 < 32; nt2++)
#pragma unroll
            for (int e = 0; e < 2; e++) {
                const int c = nt2 * 8 + 2 * jj + e;
                const float cm = csum[c];
                Os[row0 * OSS + c]       = d0 ? cm : Oacc[nt2][e] * inv0;
                Os[(row0 + 8) * OSS + c] = d1 ? cm : Oacc[nt2][2 + e] * inv1;
            }
    }
    __syncthreads();

    // ---- LayerNorm stats (2 threads per row) ----
    {
        const int r = tid >> 1, hf = tid & 1;
        const float* row = Os + r * OSS + hf * 128;
        float s1 = 0.f;
#pragma unroll 8
        for (int c = 0; c < 128; c++) s1 += row[c];
        s1 += __shfl_xor_sync(0xffffffffu, s1, 1);
        const float mu = s1 * (1.f / 256.f);
        float s2 = 0.f;
#pragma unroll 8
        for (int c = 0; c < 128; c++) { float d = row[c] - mu; s2 += d * d; }
        s2 += __shfl_xor_sync(0xffffffffu, s2, 1);
        const float rstd = rsqrtf(s2 * (1.f / 256.f) + 1e-9f);
        if (hf == 0) { smf[OF_MU / 4 + r] = mu; smf[OF_RS / 4 + r] = rstd; }
    }
    __syncthreads();

    // ---- Column partials (each thread: cols tid, tid+128) ----
    {
        float acc0 = 0.f, acc1 = 0.f;
#pragma unroll 4
        for (int r = 0; r < BR; r++) {
            const float muv = smf[OF_MU / 4 + r], rsv = smf[OF_RS / 4 + r];
            acc0 += (Os[r * OSS + tid]       - muv) * rsv;
            acc1 += (Os[r * OSS + tid + 128] - muv) * rsv;
        }
        float* gp = g_part + (size_t)(b * NTILE + qt) * C_;
        gp[tid]       = gamma[tid]       * acc0 + 64.f * beta[tid];
        gp[tid + 128] = gamma[tid + 128] * acc1 + 64.f * beta[tid + 128];
    }

    // ---- Last CTA of batch b reduces the 16 partials -> output ----
    __threadfence();
    __syncthreads();
    if (tid == 0) {
        int v = atomicAdd(&g_done[b], 1);
        lastflag = (v == NTILE - 1);
    }
    __syncthreads();
    if (lastflag) {
#pragma unroll
        for (int cc = 0; cc < 2; cc++) {
            const int c = tid + cc * 128;
            float s = 0.f;
#pragma unroll
            for (int q = 0; q < NTILE; q++)
                s += g_part[(size_t)(b * NTILE + q) * C_ + c];
            out[b * C_ + c] = s * (1.f / 1024.f);
        }
    }
}

// ---------------------------------------------------------------------------
extern "C" void kernel_launch(void* const* d_in, const int* in_sizes, int n_in,
                              void* d_out, int out_size)
{
    const float* x     = (const float*)d_in[0];
    const int*   km    = (const int*)  d_in[1];
    const float* gamma = (const float*)d_in[2];
    const float* beta  = (const float*)d_in[3];
    float*       out   = (float*)d_out;

    cudaFuncSetAttribute(attn_kernel,
                         cudaFuncAttributeMaxDynamicSharedMemorySize, SMEM_TOTAL);

    prep_kernel<<<dim3(B_, 16), 256>>>(x);
    scan_kernel<<<B_, 256>>>(km);
    attn_kernel<<<dim3(B_, NTILE), 128, SMEM_TOTAL>>>(gamma, beta, out);
}

// round 17
// speedup vs baseline: 1.1619x; 1.1619x over previous
#include <cuda_runtime.h>
#include <cuda_fp16.h>
#include <math.h>
#include <stdint.h>

// Problem constants
#define B_  64
#define T_  1024
#define C_  256
#define BR  64               // query rows per CTA (= key tile)
#define NTILE (T_ / BR)      // 16
#define OSS 260              // final O staging stride (floats)

// SMEM byte offsets (per CTA ~100.5 KB -> 2 CTAs/SM)
#define OF_Q   0             // 64 rows x 528B
#define OF_X0  33792         // 64 rows x 528B (double-buffered gathered K=V)
#define OF_X1  67584
#define OF_MU  101376        // mu[64]
#define OF_RS  101632        // rstd[64]
#define OF_CS  101888        // colsum/1024 [256] (never aliased)
#define SMEM_TOTAL 102912

#define PAD_IDX 0x3FFFFFFF

// Device scratch
__device__ __half g_xh[B_ * T_ * C_];     // fp16 copy of x
__device__ __align__(512) __half g_zeroRow[C_];  // zero-init (static storage)
__device__ int    g_kidx[B_ * T_];        // orig index per compacted key slot
__device__ int    g_cnt[B_ * NTILE];      // # valid keys with idx < (qt+1)*64
__device__ int    g_done[B_];             // per-batch completion counter
__device__ float  g_cs64[B_ * 64 * C_];   // colsum partials (16-row groups)
__device__ float  g_colsum[B_ * C_];      // pre-scaled colsum/1024
__device__ float  g_part[B_ * NTILE * C_];

// ---------------------------------------------------------------------------
static __device__ __forceinline__ uint32_t smem_u32(const void* p) {
    return (uint32_t)__cvta_generic_to_shared(p);
}
static __device__ __forceinline__ void cp16(uint32_t dst, const void* src) {
    asm volatile("cp.async.cg.shared.global [%0], [%1], 16;" :: "r"(dst), "l"(src));
}
static __device__ __forceinline__ void ldsm4(
    uint32_t& r0, uint32_t& r1, uint32_t& r2, uint32_t& r3, uint32_t a)
{
    asm volatile("ldmatrix.sync.aligned.m8n8.x4.shared.b16 {%0,%1,%2,%3}, [%4];"
                 : "=r"(r0), "=r"(r1), "=r"(r2), "=r"(r3) : "r"(a));
}
static __device__ __forceinline__ void ldsm4t(
    uint32_t& r0, uint32_t& r1, uint32_t& r2, uint32_t& r3, uint32_t a)
{
    asm volatile("ldmatrix.sync.aligned.m8n8.x4.trans.shared.b16 {%0,%1,%2,%3}, [%4];"
                 : "=r"(r0), "=r"(r1), "=r"(r2), "=r"(r3) : "r"(a));
}
static __device__ __forceinline__ void mma_f16(
    float* d, uint32_t a0, uint32_t a1, uint32_t a2, uint32_t a3,
    uint32_t b0, uint32_t b1)
{
    asm volatile(
        "mma.sync.aligned.m16n8k16.row.col.f32.f16.f16.f32 "
        "{%0,%1,%2,%3},{%4,%5,%6,%7},{%8,%9},{%0,%1,%2,%3};"
        : "+f"(d[0]), "+f"(d[1]), "+f"(d[2]), "+f"(d[3])
        : "r"(a0), "r"(a1), "r"(a2), "r"(a3), "r"(b0), "r"(b1));
}
static __device__ __forceinline__ uint32_t packh2(float x, float y) {
    __half2 h = __floats2half2_rn(x, y);
    return *(uint32_t*)&h;
}

// ---------------------------------------------------------------------------
// Per-tile compute, specialized at compile time on the number of live
// 16-key blocks NB (1..4). NB<4 only ever used for a CTA's LAST tile whose
// trailing blocks are all PAD (exact-zero contributions). CTA-uniform.
// ---------------------------------------------------------------------------
template<int NB>
static __device__ __forceinline__ void tile_step(
    uint32_t sb, uint32_t Xoff, int s0,
    int grow0, int grow1, const int* kib,
    int jj, int lane, int lh, uint32_t aQ, int l15,
    float Oacc[32][4], float& m0, float& m1, float& l0, float& l1)
{
    int2 kiv[8];
#pragma unroll
    for (int nt = 0; nt < 8; nt++)
        kiv[nt] = *(const int2*)(kib + s0 + nt * 8 + 2 * jj);

    // ---- Stage A: S = Q Kc^T, warp tile 16x64 (NB live blocks) ----
    uint32_t aK[4];
#pragma unroll
    for (int nb = 0; nb < 4; nb++)
        aK[nb] = sb + Xoff + (uint32_t)(nb * 16 + (lane & 7) + lh * 8) * 528
                 + ((lane >> 3) & 1) * 16;

    float sacc[8][4];
#pragma unroll
    for (int nt = 0; nt < 8; nt++)
#pragma unroll
        for (int e = 0; e < 4; e++) sacc[nt][e] = 0.f;

#pragma unroll
    for (int k = 0; k < 16; k++) {
        uint32_t a0, a1, a2, a3;
        ldsm4(a0, a1, a2, a3, aQ + k * 32);
#pragma unroll
        for (int nb = 0; nb < NB; nb++) {
            uint32_t b0, b1, b2, b3;
            ldsm4(b0, b1, b2, b3, aK[nb] + k * 32);
            mma_f16(sacc[2 * nb],     a0, a1, a2, a3, b0, b1);
            mma_f16(sacc[2 * nb + 1], a0, a1, a2, a3, b2, b3);
        }
    }

    // ---- Mask + in-register online softmax (full width; PAD -> p=0) ----
#pragma unroll
    for (int nt = 0; nt < 8; nt++) {
#pragma unroll
        for (int e = 0; e < 2; e++) {
            const int ki = e ? kiv[nt].y : kiv[nt].x;
            sacc[nt][e]     = (ki <= grow0) ? sacc[nt][e] * 0.0625f     : -INFINITY;
            sacc[nt][2 + e] = (ki <= grow1) ? sacc[nt][2 + e] * 0.0625f : -INFINITY;
        }
    }
    float mt0 = -INFINITY, mt1 = -INFINITY;
#pragma unroll
    for (int nt = 0; nt < 8; nt++) {
        mt0 = fmaxf(mt0, fmaxf(sacc[nt][0], sacc[nt][1]));
        mt1 = fmaxf(mt1, fmaxf(sacc[nt][2], sacc[nt][3]));
    }
    mt0 = fmaxf(mt0, __shfl_xor_sync(0xffffffffu, mt0, 1));
    mt0 = fmaxf(mt0, __shfl_xor_sync(0xffffffffu, mt0, 2));
    mt1 = fmaxf(mt1, __shfl_xor_sync(0xffffffffu, mt1, 1));
    mt1 = fmaxf(mt1, __shfl_xor_sync(0xffffffffu, mt1, 2));
    const float mn0 = fmaxf(m0, mt0), mn1 = fmaxf(m1, mt1);
    const float al0 = (m0 == -INFINITY) ? 0.f : __expf(m0 - mn0);
    const float al1 = (m1 == -INFINITY) ? 0.f : __expf(m1 - mn1);

    float p0[8][2], p1[8][2], sum0 = 0.f, sum1 = 0.f;
#pragma unroll
    for (int nt = 0; nt < 8; nt++) {
#pragma unroll
        for (int e = 0; e < 2; e++) {
            float a = sacc[nt][e],     pa = (a == -INFINITY) ? 0.f : __expf(a - mn0);
            float c = sacc[nt][2 + e], pc = (c == -INFINITY) ? 0.f : __expf(c - mn1);
            p0[nt][e] = pa; sum0 += pa;
            p1[nt][e] = pc; sum1 += pc;
        }
    }
    sum0 += __shfl_xor_sync(0xffffffffu, sum0, 1);
    sum0 += __shfl_xor_sync(0xffffffffu, sum0, 2);
    sum1 += __shfl_xor_sync(0xffffffffu, sum1, 1);
    sum1 += __shfl_xor_sync(0xffffffffu, sum1, 2);
    l0 = l0 * al0 + sum0;  m0 = mn0;
    l1 = l1 * al1 + sum1;  m1 = mn1;

#pragma unroll
    for (int i = 0; i < 32; i++) {
        Oacc[i][0] *= al0; Oacc[i][1] *= al0;
        Oacc[i][2] *= al1; Oacc[i][3] *= al1;
    }

    uint32_t pA[4][4];
#pragma unroll
    for (int kb = 0; kb < 4; kb++) {
        pA[kb][0] = packh2(p0[2 * kb][0],     p0[2 * kb][1]);
        pA[kb][1] = packh2(p1[2 * kb][0],     p1[2 * kb][1]);
        pA[kb][2] = packh2(p0[2 * kb + 1][0], p0[2 * kb + 1][1]);
        pA[kb][3] = packh2(p1[2 * kb + 1][0], p1[2 * kb + 1][1]);
    }

    // ---- Stage B: O += P @ Xc (NB live key-chunks; P==0 beyond) ----
    const uint32_t aXb = sb + Xoff + (uint32_t)l15 * 528 + lh * 16;
#pragma unroll
    for (int ks = 0; ks < NB; ks++) {
#pragma unroll
        for (int n16 = 0; n16 < 16; n16++) {
            uint32_t x0, x1, x2, x3;
            ldsm4t(x0, x1, x2, x3, aXb + ks * 16 * 528 + n16 * 32);
            mma_f16(Oacc[2 * n16],     pA[ks][0], pA[ks][1], pA[ks][2], pA[ks][3], x0, x1);
            mma_f16(Oacc[2 * n16 + 1], pA[ks][0], pA[ks][1], pA[ks][2], pA[ks][3], x2, x3);
        }
    }
}

// ---------------------------------------------------------------------------
// Kernel 1: fp16 copy of x (vectorized) + fp32 colsum partials
// ---------------------------------------------------------------------------
__global__ void prep_kernel(const float* __restrict__ x) {
    const int b = blockIdx.x, ch = blockIdx.y, tid = threadIdx.x;
    const int c4 = (tid & 63) * 4;
    const int rg = tid >> 6;                  // 0..3
    const size_t row0 = (size_t)b * T_ + ch * 64 + rg * 16;
    float s0 = 0.f, s1 = 0.f, s2 = 0.f, s3 = 0.f;
#pragma unroll
    for (int i = 0; i < 16; i++) {
        const float4 v = *(const float4*)(x + (row0 + i) * C_ + c4);
        s0 += v.x; s1 += v.y; s2 += v.z; s3 += v.w;
        __half2 h0 = __floats2half2_rn(v.x, v.y);
        __half2 h1 = __floats2half2_rn(v.z, v.w);
        *(uint2*)(g_xh + (row0 + i) * C_ + c4) =
            make_uint2(*(uint32_t*)&h0, *(uint32_t*)&h1);
    }
    *(float4*)(g_cs64 + ((size_t)(b * 64 + ch * 4 + rg)) * C_ + c4) =
        make_float4(s0, s1, s2, s3);
}

// ---------------------------------------------------------------------------
// Kernel 1b: per-batch scan (prefix-sum of key mask) + colsum reduce + done=0
// ---------------------------------------------------------------------------
__global__ void scan_kernel(const int* __restrict__ km) {
    __shared__ int list[T_];
    __shared__ int wsum[8];
    __shared__ int incl[256];
    __shared__ int total_s;

    const int b = blockIdx.x, tid = threadIdx.x;
    const int lane = tid & 31, wp = tid >> 5;

    if (tid == 0) g_done[b] = 0;

    int4 f = ((const int4*)(km + b * T_))[tid];
    int c0 = (f.x != 0), c1 = (f.y != 0), c2 = (f.z != 0), c3 = (f.w != 0);
    int cnt4 = c0 + c1 + c2 + c3;

    int v = cnt4;
#pragma unroll
    for (int off = 1; off < 32; off <<= 1) {
        int n = __shfl_up_sync(0xffffffffu, v, off);
        if (lane >= off) v += n;
    }
    if (lane == 31) wsum[wp] = v;
    __syncthreads();
    if (tid == 0) {
        int running = 0;
#pragma unroll
        for (int i = 0; i < 8; i++) { int t = wsum[i]; wsum[i] = running; running += t; }
        total_s = running;
    }
    __syncthreads();
    const int excl = v - cnt4 + wsum[wp];
    incl[tid] = excl + cnt4;

    int base = excl;
    const int t0 = tid * 4;
    if (c0) list[base++] = t0;
    if (c1) list[base++] = t0 + 1;
    if (c2) list[base++] = t0 + 2;
    if (c3) list[base++] = t0 + 3;
    __syncthreads();

    if (tid < NTILE) g_cnt[b * NTILE + tid] = incl[(tid + 1) * 16 - 1];

    const int nv = total_s;
    const int nvp = (nv + 63) & ~63;
    for (int r = tid; r < nvp; r += 256)
        g_kidx[b * T_ + r] = (r < nv) ? list[r] : PAD_IDX;

    float s = 0.f;
#pragma unroll 8
    for (int i = 0; i < 64; i++) s += g_cs64[(size_t)(b * 64 + i) * C_ + tid];
    g_colsum[b * C_ + tid] = s * (1.f / 1024.f);
}

// ---------------------------------------------------------------------------
// Kernel 2: flash attention over compacted keys (gathered on load), fp16 mma,
// register P, in-register online softmax. Last tile uses compile-time-
// specialized PAD-block skip (CTA-uniform). 128 thr, 2 CTAs/SM.
// ---------------------------------------------------------------------------
__global__ void __launch_bounds__(128, 2)
attn_kernel(const float* __restrict__ gamma, const float* __restrict__ beta,
            float* __restrict__ out)
{
    extern __shared__ char smc[];
    __shared__ int lastflag;
    float* smf = (float*)smc;
    const uint32_t sb = smem_u32(smc);

    const int qt   = 15 - blockIdx.y;        // heavy tiles first
    const int b    = blockIdx.x;
    const int tid  = threadIdx.x;
    const int lane = tid & 31;
    const int w    = tid >> 5;
    const int jj   = lane & 3;
    const int g8   = lane >> 2;
    const int l15  = lane & 15;
    const int lh   = lane >> 4;
    const int q0   = qt * BR;
    const int row0 = w * 16 + g8;
    const int grow0 = q0 + row0, grow1 = grow0 + 8;
    const __half* xb  = g_xh + (size_t)b * T_ * C_;
    const int*    kib = g_kidx + b * T_;

    const int cnt    = g_cnt[b * NTILE + qt];
    const int ntiles = (cnt + 63) >> 6;
    const int nblive = ntiles ? ((cnt - (ntiles - 1) * 64 + 15) >> 4) : 0; // 1..4

    const uint32_t aQ = sb + OF_Q + (uint32_t)(w * 16 + l15) * 528 + lh * 16;

    // Prefetch Q (+ gathered key tile 0 if any)
#pragma unroll
    for (int it = 0; it < 16; it++) {
        int idx = tid + it * 128;
        int r = idx >> 5, g = idx & 31;
        cp16(sb + OF_Q + r * 528 + g * 16, xb + (size_t)(q0 + r) * C_ + g * 8);
    }
    if (ntiles > 0) {
#pragma unroll
        for (int it = 0; it < 16; it++) {
            int idx = tid + it * 128;
            int r = idx >> 5, g = idx & 31;
            const int orig = kib[r];
            const __half* src = (orig == PAD_IDX) ? g_zeroRow
                                                  : xb + (size_t)orig * C_;
            cp16(sb + OF_X0 + r * 528 + g * 16, src + g * 8);
        }
    }
    asm volatile("cp.async.commit_group;");

    float Oacc[32][4];
#pragma unroll
    for (int i = 0; i < 32; i++)
#pragma unroll
        for (int e = 0; e < 4; e++) Oacc[i][e] = 0.f;
    float m0 = -INFINITY, m1 = -INFINITY, l0 = 0.f, l1 = 0.f;

    for (int st = 0; st < ntiles; st++) {
        const uint32_t Xoff = (st & 1) ? OF_X1 : OF_X0;
        const int s0 = st * BR;

        asm volatile("cp.async.wait_group 0;");
        __syncthreads();                      // X[st] visible; other buffer free

        if (st + 1 < ntiles) {                // prefetch next gathered tile
            const uint32_t Xn = ((st + 1) & 1) ? OF_X1 : OF_X0;
            const int s0n = (st + 1) * BR;
#pragma unroll
            for (int it = 0; it < 16; it++) {
                int idx = tid + it * 128;
                int r = idx >> 5, g = idx & 31;
                const int orig = kib[s0n + r];
                const __half* src = (orig == PAD_IDX) ? g_zeroRow
                                                      : xb + (size_t)orig * C_;
                cp16(sb + Xn + r * 528 + g * 16, src + g * 8);
            }
            asm volatile("cp.async.commit_group;");
        }

        if (st + 1 < ntiles) {
            // full tile — identical schedule to the R15 hot loop
            tile_step<4>(sb, Xoff, s0, grow0, grow1, kib, jj, lane, lh, aQ, l15,
                         Oacc, m0, m1, l0, l1);
        } else {
            // last tile — CTA-uniform compile-time PAD-block skip
            switch (nblive) {
                case 1: tile_step<1>(sb, Xoff, s0, grow0, grow1, kib, jj, lane, lh, aQ, l15,
                                     Oacc, m0, m1, l0, l1); break;
                case 2: tile_step<2>(sb, Xoff, s0, grow0, grow1, kib, jj, lane, lh, aQ, l15,
                                     Oacc, m0, m1, l0, l1); break;
                case 3: tile_step<3>(sb, Xoff, s0, grow0, grow1, kib, jj, lane, lh, aQ, l15,
                                     Oacc, m0, m1, l0, l1); break;
                default: tile_step<4>(sb, Xoff, s0, grow0, grow1, kib, jj, lane, lh, aQ, l15,
                                      Oacc, m0, m1, l0, l1); break;
            }
        }
    }
    asm volatile("cp.async.wait_group 0;");    // drain (covers ntiles==0)

    // ---- colsum (pre-scaled, pre-reduced) -> never-aliased smem ----
    smf[OF_CS / 4 + tid]       = g_colsum[b * C_ + tid];
    smf[OF_CS / 4 + tid + 128] = g_colsum[b * C_ + tid + 128];

    // ---- Epilogue: normalize / degenerate fixup -> Os staging ----
    __syncthreads();
    float* Os = smf;
    const float* csum = smf + OF_CS / 4;
    {
        const bool d0 = (l0 == 0.f), d1 = (l1 == 0.f);
        const float inv0 = d0 ? 0.f : (1.f / l0);
        const float inv1 = d1 ? 0.f : (1.f / l1);
#pragma unroll
        for (int nt2 = 0; nt2 < 32; nt2++)
#pragma unroll
            for (int e = 0; e < 2; e++) {
                const int c = nt2 * 8 + 2 * jj + e;
                const float cm = csum[c];
                Os[row0 * OSS + c]       = d0 ? cm : Oacc[nt2][e] * inv0;
                Os[(row0 + 8) * OSS + c] = d1 ? cm : Oacc[nt2][2 + e] * inv1;
            }
    }
    __syncthreads();

    // ---- LayerNorm stats (2 threads per row) ----
    {
        const int r = tid >> 1, hf = tid & 1;
        const float* row = Os + r * OSS + hf * 128;
        float s1 = 0.f;
#pragma unroll 8
        for (int c = 0; c < 128; c++) s1 += row[c];
        s1 += __shfl_xor_sync(0xffffffffu, s1, 1);
        const float mu = s1 * (1.f / 256.f);
        float s2 = 0.f;
#pragma unroll 8
        for (int c = 0; c < 128; c++) { float d = row[c] - mu; s2 += d * d; }
        s2 += __shfl_xor_sync(0xffffffffu, s2, 1);
        const float rstd = rsqrtf(s2 * (1.f / 256.f) + 1e-9f);
        if (hf == 0) { smf[OF_MU / 4 + r] = mu; smf[OF_RS / 4 + r] = rstd; }
    }
    __syncthreads();

    // ---- Column partials (each thread: cols tid, tid+128) ----
    {
        float acc0 = 0.f, acc1 = 0.f;
#pragma unroll 4
        for (int r = 0; r < BR; r++) {
            const float muv = smf[OF_MU / 4 + r], rsv = smf[OF_RS / 4 + r];
            acc0 += (Os[r * OSS + tid]       - muv) * rsv;
            acc1 += (Os[r * OSS + tid + 128] - muv) * rsv;
        }
        float* gp = g_part + (size_t)(b * NTILE + qt) * C_;
        gp[tid]       = gamma[tid]       * acc0 + 64.f * beta[tid];
        gp[tid + 128] = gamma[tid + 128] * acc1 + 64.f * beta[tid + 128];
    }

    // ---- Last CTA of batch b reduces the 16 partials -> output ----
    __threadfence();
    __syncthreads();
    if (tid == 0) {
        int v = atomicAdd(&g_done[b], 1);
        lastflag = (v == NTILE - 1);
    }
    __syncthreads();
    if (lastflag) {
#pragma unroll
        for (int cc = 0; cc < 2; cc++) {
            const int c = tid + cc * 128;
            float s = 0.f;
#pragma unroll
            for (int q = 0; q < NTILE; q++)
                s += g_part[(size_t)(b * NTILE + q) * C_ + c];
            out[b * C_ + c] = s * (1.f / 1024.f);
        }
    }
}

// ---------------------------------------------------------------------------
extern "C" void kernel_launch(void* const* d_in, const int* in_sizes, int n_in,
                              void* d_out, int out_size)
{
    const float* x     = (const float*)d_in[0];
    const int*   km    = (const int*)  d_in[1];
    const float* gamma = (const float*)d_in[2];
    const float* beta  = (const float*)d_in[3];
    float*       out   = (float*)d_out;

    cudaFuncSetAttribute(attn_kernel,
                         cudaFuncAttributeMaxDynamicSharedMemorySize, SMEM_TOTAL);

    prep_kernel<<<dim3(B_, 16), 256>>>(x);
    scan_kernel<<<B_, 256>>>(km);
    attn_kernel<<<dim3(B_, NTILE), 128, SMEM_TOTAL>>>(gamma, beta, out);
}